// round 5
// baseline (speedup 1.0000x reference)
#include <cuda_runtime.h>

// PIF integrate-and-fire, closed form: s = clamp(floor(x + 0.5f), 0, 8).
// Pure HBM stream: 205.5 MB in + 205.5 MB out.
//
// R5: persistent single-wave kernel. n4 = 12845056 = 2^18 * 49 divides
// exactly as 1024 blocks x 256 threads x 49 float4s/thread. One wave of
// CTAs (<= ~7/SM), zero wave transitions, zero guards. Inner structure:
// 7 groups of 7 front-batched LDG.128s (MLP=7 per group).
// Guarded fallback kernel for any other size (deterministic dispatch).

#define P_BLOCKS 1024
#define P_THREADS 256
#define P_ITERS 49   // float4s per thread; 7 groups of 7

__global__ void __launch_bounds__(P_THREADS)
pif_kernel_persist(const float4* __restrict__ x, float4* __restrict__ out) {
    const int total = P_BLOCKS * P_THREADS;          // 262144
    int i0 = blockIdx.x * P_THREADS + threadIdx.x;

#pragma unroll
    for (int g = 0; g < 7; g++) {
        float4 v[7];
#pragma unroll
        for (int j = 0; j < 7; j++)
            v[j] = __ldcs(&x[i0 + (g * 7 + j) * total]);
#pragma unroll
        for (int j = 0; j < 7; j++) {
            float4 r;
            r.x = fminf(8.0f, fmaxf(0.0f, floorf(v[j].x + 0.5f)));
            r.y = fminf(8.0f, fmaxf(0.0f, floorf(v[j].y + 0.5f)));
            r.z = fminf(8.0f, fmaxf(0.0f, floorf(v[j].z + 0.5f)));
            r.w = fminf(8.0f, fmaxf(0.0f, floorf(v[j].w + 0.5f)));
            __stcs(&out[i0 + (g * 7 + j) * total], r);
        }
    }
}

#define VPT 4
__global__ void __launch_bounds__(256)
pif_kernel_guarded(const float4* __restrict__ x, float4* __restrict__ out, int n4) {
    int base = blockIdx.x * (256 * VPT) + threadIdx.x;

    float4 v[VPT];
    bool ok[VPT];
#pragma unroll
    for (int k = 0; k < VPT; k++) {
        int i = base + k * 256;
        ok[k] = i < n4;
        if (ok[k]) v[k] = __ldcs(&x[i]);
    }
#pragma unroll
    for (int k = 0; k < VPT; k++) {
        float4 r;
        r.x = fminf(8.0f, fmaxf(0.0f, floorf(v[k].x + 0.5f)));
        r.y = fminf(8.0f, fmaxf(0.0f, floorf(v[k].y + 0.5f)));
        r.z = fminf(8.0f, fmaxf(0.0f, floorf(v[k].z + 0.5f)));
        r.w = fminf(8.0f, fmaxf(0.0f, floorf(v[k].w + 0.5f)));
        if (ok[k]) __stcs(&out[base + k * 256], r);
    }
}

// Tail for out_size % 4 != 0 (not hit here).
__global__ void pif_tail_kernel(const float* __restrict__ x, float* __restrict__ out,
                                int start, int n) {
    int i = start + blockIdx.x * blockDim.x + threadIdx.x;
    if (i < n) {
        out[i] = fminf(8.0f, fmaxf(0.0f, floorf(x[i] + 0.5f)));
    }
}

extern "C" void kernel_launch(void* const* d_in, const int* in_sizes, int n_in,
                              void* d_out, int out_size) {
    const float* x = (const float*)d_in[0];
    float* out = (float*)d_out;
    int n = out_size;

    int n4 = n / 4;
    if (n4 == P_BLOCKS * P_THREADS * P_ITERS) {
        pif_kernel_persist<<<P_BLOCKS, P_THREADS>>>((const float4*)x, (float4*)out);
    } else if (n4 > 0) {
        const int epb = 256 * VPT;
        pif_kernel_guarded<<<(n4 + epb - 1) / epb, 256>>>(
            (const float4*)x, (float4*)out, n4);
    }
    int rem = n - n4 * 4;
    if (rem > 0) {
        pif_tail_kernel<<<1, 256>>>(x, out, n4 * 4, n);
    }
}